// round 9
// baseline (speedup 1.0000x reference)
#include <cuda_runtime.h>
#include <cuda_bf16.h>
#include <cuda_pipeline.h>

#define TPB 256
#define WPB (TPB / 32)        // 8 warps per block
#define GPW 64                // gaussians per warp per tile (2 per lane)
#define GPB (WPB * GPW)       // 512 gaussians per block-tile

// per-warp smem layout (floats):
//   stage0 [0,448): 256 quat + 192 scales
//   stage1 [448,896)
//   out    [896,1472)
#define STG_F   448
#define OFF_S   256
#define SLICE_F 1472           // 5888 B/warp -> 47104 B/block (under 48KB static limit)

__device__ __forceinline__ void cov_from_q(float4 qv, float s0, float s1, float s2,
                                           float* __restrict__ o /* 9 floats */)
{
    float r = qv.x, x = qv.y, y = qv.z, z = qv.w;
    float n2  = r*r + x*x + y*y + z*z;
    float inv = rsqrtf(fmaxf(n2, 1e-24f));   // == 1/max(||q||,1e-12)
    r *= inv; x *= inv; y *= inv; z *= inv;

    float R00 = 1.0f - 2.0f*(y*y + z*z);
    float R01 = 2.0f*(x*y - r*z);
    float R02 = 2.0f*(x*z + r*y);
    float R10 = 2.0f*(x*y + r*z);
    float R11 = 1.0f - 2.0f*(x*x + z*z);
    float R12 = 2.0f*(y*z - r*x);
    float R20 = 2.0f*(x*z - r*y);
    float R21 = 2.0f*(y*z + r*x);
    float R22 = 1.0f - 2.0f*(x*x + y*y);

    float t0 = s0*s0, t1 = s1*s1, t2 = s2*s2;

    float c01 = R00*R10*t0 + R01*R11*t1 + R02*R12*t2;
    float c02 = R00*R20*t0 + R01*R21*t1 + R02*R22*t2;
    float c12 = R10*R20*t0 + R11*R21*t1 + R12*R22*t2;
    o[0] = R00*R00*t0 + R01*R01*t1 + R02*R02*t2;
    o[1] = c01;
    o[2] = c02;
    o[3] = c01;
    o[4] = R10*R10*t0 + R11*R11*t1 + R12*R12*t2;
    o[5] = c12;
    o[6] = c02;
    o[7] = c12;
    o[8] = R20*R20*t0 + R21*R21*t1 + R22*R22*t2;
}

__global__ __launch_bounds__(TPB, 4) void gaussians_cov_kernel(
    const float4* __restrict__ quat,   // [n] as float4 (r,x,y,z)
    const float*  __restrict__ scales, // [n*3]
    float*        __restrict__ out,    // [n*9]
    int n)
{
    __shared__ float smem[WPB * SLICE_F];

    const int wid  = threadIdx.x >> 5;
    const int lane = threadIdx.x & 31;

    float* ws   = smem + wid * SLICE_F;
    float* stg0 = ws;
    float* stg1 = ws + STG_F;
    float* wout = ws + 2 * STG_F;

    const int nTiles = (n + GPB - 1) / GPB;
    const int stride = gridDim.x;

    // ---- prime the pipeline: prefetch first tile ----
    int t0i = blockIdx.x;
    bool curFull = false;
    if (t0i < nTiles) {
        int wb = t0i * GPB + wid * GPW;
        curFull = (wb + GPW <= n);
        if (curFull) {
            const float4* qsrc = quat + wb;
            __pipeline_memcpy_async(&stg0[lane * 4],        &qsrc[lane],      16);
            __pipeline_memcpy_async(&stg0[(32 + lane) * 4], &qsrc[32 + lane], 16);
            const float* ssrc = scales + (size_t)wb * 3;
            __pipeline_memcpy_async(&stg0[OFF_S + lane * 4], &ssrc[lane * 4], 16);
            if (lane < 16)
                __pipeline_memcpy_async(&stg0[OFF_S + (32 + lane) * 4],
                                        &ssrc[(32 + lane) * 4], 16);
        }
    }
    __pipeline_commit();

    int buf = 0;
    for (int t = t0i; t < nTiles; t += stride) {
        // ---- prefetch next tile into the other stage (1 group/iter, always) ----
        int nt = t + stride;
        bool nextFull = false;
        if (nt < nTiles) {
            int nwb = nt * GPB + wid * GPW;
            nextFull = (nwb + GPW <= n);
            if (nextFull) {
                float* s = buf ? stg0 : stg1;
                const float4* qsrc = quat + nwb;
                __pipeline_memcpy_async(&s[lane * 4],        &qsrc[lane],      16);
                __pipeline_memcpy_async(&s[(32 + lane) * 4], &qsrc[32 + lane], 16);
                const float* ssrc = scales + (size_t)nwb * 3;
                __pipeline_memcpy_async(&s[OFF_S + lane * 4], &ssrc[lane * 4], 16);
                if (lane < 16)
                    __pipeline_memcpy_async(&s[OFF_S + (32 + lane) * 4],
                                            &ssrc[(32 + lane) * 4], 16);
            }
        }
        __pipeline_commit();
        __pipeline_wait_prior(1);      // current stage ready; next stays in flight
        __syncwarp();                  // also orders prev writeback before wout reuse

        int wb = t * GPB + wid * GPW;
        if (curFull) {
            float* s = buf ? stg1 : stg0;
            // compute 2 covariances from smem stage (stride-3 LDS conflict-free)
            #pragma unroll
            for (int j = 0; j < 2; j++) {
                int tt = j * 32 + lane;
                float4 qv = *reinterpret_cast<const float4*>(&s[tt * 4]);
                cov_from_q(qv, s[OFF_S + tt*3 + 0], s[OFF_S + tt*3 + 1],
                               s[OFF_S + tt*3 + 2], &wout[tt * 9]);
            }
            __syncwarp();
            // coalesced streaming writeback: 144 float4 per warp
            float4*       o4 = reinterpret_cast<float4*>(out + (size_t)wb * 9);
            const float4* s4 = reinterpret_cast<const float4*>(wout);
            #pragma unroll
            for (int k = lane; k < (9 * GPW) / 4; k += 32)
                __stcs(&o4[k], s4[k]);
        } else if (wb < n) {
            // tail: guarded scalar path
            for (int g = wb + lane; g < n && g < wb + GPW; g += 32) {
                float4 qv = quat[g];
                float  oo[9];
                cov_from_q(qv, scales[(size_t)g*3+0], scales[(size_t)g*3+1],
                               scales[(size_t)g*3+2], oo);
                #pragma unroll
                for (int k = 0; k < 9; k++)
                    out[(size_t)g * 9 + k] = oo[k];
            }
        }
        curFull = nextFull;
        buf ^= 1;
    }
}

extern "C" void kernel_launch(void* const* d_in, const int* in_sizes, int n_in,
                              void* d_out, int out_size) {
    const float4* quat   = (const float4*)d_in[0];   // quaternions [n,4]
    const float*  scales = (const float*)d_in[1];    // scales [n,3]
    float*        out    = (float*)d_out;            // covariance [n,3,3]
    int n = in_sizes[0] / 4;

    int nTiles = (n + GPB - 1) / GPB;
    int blocks = 148 * 4;                 // persistent: fill 4 blocks/SM
    if (blocks > nTiles) blocks = nTiles;
    gaussians_cov_kernel<<<blocks, TPB>>>(quat, scales, out, n);
}